// round 6
// baseline (speedup 1.0000x reference)
#include <cuda_runtime.h>
#include <math.h>

#define BB 4
#define SS 2048
#define DD 1024
#define HH 16
#define HD 64
#define MROWS (BB * SS)   // 8192

// Scratch (allocation-free: __device__ globals)
__device__ float g_K[BB * HH * SS * HD];
__device__ float g_Q[BB * HH * SS * HD];
__device__ float g_V[BB * HH * SS * HD];
__device__ float g_Y[BB * SS * DD];
__device__ float g_xr[MROWS * DD];     // x rounded to tf32
__device__ float g_Wa[3 * DD * DD];    // W_attn rounded
__device__ float g_Wo[DD * DD];        // W_out rounded

// ---------------------------------------------------------------------------
// helpers
// ---------------------------------------------------------------------------
__device__ __forceinline__ unsigned f2t(float f) {
    unsigned u;
    asm("cvt.rna.tf32.f32 %0, %1;" : "=r"(u) : "f"(f));
    return u;
}

__device__ __forceinline__ void mma8(float* c, const unsigned* a, const unsigned* b) {
    asm volatile(
        "mma.sync.aligned.m16n8k8.row.col.f32.tf32.tf32.f32 "
        "{%0,%1,%2,%3}, {%4,%5,%6,%7}, {%8,%9}, {%0,%1,%2,%3};\n"
        : "+f"(c[0]), "+f"(c[1]), "+f"(c[2]), "+f"(c[3])
        : "r"(a[0]), "r"(a[1]), "r"(a[2]), "r"(a[3]), "r"(b[0]), "r"(b[1]));
}

__device__ __forceinline__ void cpa16(void* s, const void* g) {
    unsigned sa = (unsigned)__cvta_generic_to_shared(s);
    asm volatile("cp.async.cg.shared.global [%0], [%1], 16;\n"
                 :: "r"(sa), "l"(g) : "memory");
}
__device__ __forceinline__ void cp_commit() {
    asm volatile("cp.async.commit_group;\n" ::: "memory");
}
template <int N>
__device__ __forceinline__ void cp_wait() {
    asm volatile("cp.async.wait_group %0;\n" :: "n"(N) : "memory");
}

// ---------------------------------------------------------------------------
// Prep: round tensors to tf32-representable fp32 (TGT: 0=x, 1=W_attn, 2=W_out)
// ---------------------------------------------------------------------------
template <int TGT>
__global__ void round_tf32_k(const float* __restrict__ in, int n4) {
    float* outp = (TGT == 0) ? g_xr : (TGT == 1) ? g_Wa : g_Wo;
    int i = blockIdx.x * blockDim.x + threadIdx.x;
    if (i < n4) {
        float4 v = ((const float4*)in)[i];
        float4 o;
        o.x = __uint_as_float(f2t(v.x));
        o.y = __uint_as_float(f2t(v.y));
        o.z = __uint_as_float(f2t(v.z));
        o.w = __uint_as_float(f2t(v.w));
        ((float4*)outp)[i] = o;
    }
}

// ---------------------------------------------------------------------------
// TF32 GEMM, 4-stage cp.async pipeline, 16-k stages, ONE barrier per stage.
// C[m,n] = sum_k A[m,k]*W[n,k] + bias[n]. BLK 128x128, 256 thr (8 warps
// 4m x 2n), warp tile 32x64.
// Safety: with 4 buffers, the load into slot (kt+2)&3 at iter kt happens
// after barrier B_{kt-1}, whose release implies all warps completed iter
// kt-2 — the last reader of that slot. So no end-of-stage barrier needed.
// EPI==0: A=g_xr, W=g_Wa, scatter rounded into g_K/g_Q/g_V (split k,q,v)
// EPI==1: A=g_Y,  W=g_Wo, plain fp32 store + bias
// Dynamic smem: 2 operands x 4 stages x 128x20 floats = 81920 B.
// ---------------------------------------------------------------------------
#define KST 16
#define GSTR 20            // stage row stride (floats): frag LDS conflict-free
#define STGF (128 * GSTR)  // 2560 floats per operand stage
#define NSTG 4

template <int EPI>
__global__ __launch_bounds__(256, 2) void gemm_tc(
    const float* __restrict__ bias, float* __restrict__ out)
{
    const float* A = (EPI == 0) ? (const float*)g_xr : (const float*)g_Y;
    const float* W = (EPI == 0) ? (const float*)g_Wa : (const float*)g_Wo;
    extern __shared__ float dsm[];
    float* Asm = dsm;                  // [NSTG][STGF]
    float* Bsm = dsm + NSTG * STGF;    // [NSTG][STGF]

    const int t = threadIdx.x, lane = t & 31, warp = t >> 5;
    const int wm = warp & 3, wn = warp >> 2;
    const int r = lane >> 2, c = lane & 3;
    const int mBase = blockIdx.y * 128, nBase = blockIdx.x * 128;

    float acc[2][8][4];
#pragma unroll
    for (int i = 0; i < 2; i++)
#pragma unroll
        for (int j = 0; j < 8; j++)
#pragma unroll
            for (int q = 0; q < 4; q++) acc[i][j][q] = 0.f;

    // stage loader: 128 rows x 4 float4 per operand (512 cp.async / 256 thr)
    auto load_stage = [&](int s, int k0) {
#pragma unroll
        for (int u0 = 0; u0 < 2; u0++) {
            int u = t + u0 * 256;          // 0..511
            int row = u >> 2, cg = u & 3;
            cpa16(&Asm[s * STGF + row * GSTR + cg * 4],
                  &A[(size_t)(mBase + row) * 1024 + k0 + cg * 4]);
            cpa16(&Bsm[s * STGF + row * GSTR + cg * 4],
                  &W[(size_t)(nBase + row) * 1024 + k0 + cg * 4]);
        }
        cp_commit();
    };

    load_stage(0, 0);
    load_stage(1, KST);

    for (int kt = 0; kt < 64; kt++) {
        if (kt < 62) {
            load_stage((kt + 2) & 3, (kt + 2) * KST);
            cp_wait<2>();
        } else if (kt == 62) {
            cp_wait<1>();
        } else {
            cp_wait<0>();
        }
        __syncthreads();                   // stage kt visible; sole barrier

        const float* Ab = &Asm[(kt & 3) * STGF];
        const float* Bb = &Bsm[(kt & 3) * STGF];
#pragma unroll
        for (int kk = 0; kk < 2; kk++) {
            unsigned a[2][4], b[8][2];
#pragma unroll
            for (int i = 0; i < 2; i++) {
                int m0 = wm * 32 + i * 16;
                a[i][0] = __float_as_uint(Ab[(m0 + r) * GSTR + kk * 8 + c]);
                a[i][1] = __float_as_uint(Ab[(m0 + r + 8) * GSTR + kk * 8 + c]);
                a[i][2] = __float_as_uint(Ab[(m0 + r) * GSTR + kk * 8 + c + 4]);
                a[i][3] = __float_as_uint(Ab[(m0 + r + 8) * GSTR + kk * 8 + c + 4]);
            }
#pragma unroll
            for (int j = 0; j < 8; j++) {
                int n0 = wn * 64 + j * 8 + r;
                b[j][0] = __float_as_uint(Bb[n0 * GSTR + kk * 8 + c]);
                b[j][1] = __float_as_uint(Bb[n0 * GSTR + kk * 8 + c + 4]);
            }
#pragma unroll
            for (int i = 0; i < 2; i++)
#pragma unroll
                for (int j = 0; j < 8; j++)
                    mma8(acc[i][j], a[i], b[j]);
        }
    }

#pragma unroll
    for (int i = 0; i < 2; i++) {
#pragma unroll
        for (int j = 0; j < 8; j++) {
            int mg0 = mBase + wm * 32 + i * 16 + r;
            int ng = nBase + wn * 64 + j * 8 + 2 * c;
            if (EPI == 0) {
#pragma unroll
                for (int h = 0; h < 2; h++) {
                    int m = mg0 + h * 8;
                    int bb = m >> 11, s = m & 2047;
#pragma unroll
                    for (int e = 0; e < 2; e++) {
                        int n = ng + e;
                        float v = acc[i][j][h * 2 + e] + bias[n];
                        int chunk = n >> 10;   // 0=k,1=q,2=v
                        int d = n & 1023;
                        int hh = d >> 6, hd = d & 63;
                        size_t idx = ((size_t)(bb * HH + hh) * SS + s) * HD + hd;
                        float vr = __uint_as_float(f2t(v));
                        if (chunk == 0)      g_K[idx] = vr;
                        else if (chunk == 1) g_Q[idx] = vr;
                        else                 g_V[idx] = vr;
                    }
                }
            } else {
                float2 bv = *(const float2*)&bias[ng];
                *(float2*)&out[(size_t)mg0 * DD + ng] =
                    make_float2(acc[i][j][0] + bv.x, acc[i][j][1] + bv.y);
                *(float2*)&out[(size_t)(mg0 + 8) * DD + ng] =
                    make_float2(acc[i][j][2] + bv.x, acc[i][j][3] + bv.y);
            }
        }
    }
}

// ---------------------------------------------------------------------------
// Flash attention v2 (unchanged from round 4): 128 threads, 4 warps,
// CTA tile 64 q x 64 kv, warp tile 16x64, Q in regs, softmax in regs.
// ---------------------------------------------------------------------------
#define AST 68
#define VST 72

__global__ __launch_bounds__(128) void attn_tc()
{
    extern __shared__ float dsa[];
    float* Ks = dsa;                      // [2][64][AST]
    float* Vs = Ks + 2 * 64 * AST;        // [2][64][VST]
    float* Ps = Vs + 2 * 64 * VST;        // [4][16][AST] per-warp

    const int t = threadIdx.x, lane = t & 31, w = t >> 5;
    const int r = lane >> 2, c = lane & 3;
    const int bh = blockIdx.x, mblk = blockIdx.y;

    const float* Qg  = g_Q + ((size_t)bh * SS + mblk * 64) * HD;
    const float* Kg0 = g_K + (size_t)bh * SS * HD;
    const float* Vg0 = g_V + (size_t)bh * SS * HD;

    float* Pw = Ps + w * 16 * AST;

    unsigned qa[8][4];
#pragma unroll
    for (int kk = 0; kk < 8; kk++) {
        qa[kk][0] = __float_as_uint(Qg[(w * 16 + r) * 64 + kk * 8 + c] * 0.125f);
        qa[kk][1] = __float_as_uint(Qg[(w * 16 + r + 8) * 64 + kk * 8 + c] * 0.125f);
        qa[kk][2] = __float_as_uint(Qg[(w * 16 + r) * 64 + kk * 8 + c + 4] * 0.125f);
        qa[kk][3] = __float_as_uint(Qg[(w * 16 + r + 8) * 64 + kk * 8 + c + 4] * 0.125f);
    }

    auto load_kv = [&](int s, int jt) {
        const float* Kg = Kg0 + (size_t)jt * 64 * HD;
        const float* Vg = Vg0 + (size_t)jt * 64 * HD;
#pragma unroll
        for (int u0 = 0; u0 < 8; u0++) {
            int u = t + u0 * 128;
            int row = u >> 4, cg = u & 15;
            cpa16(&Ks[s * 64 * AST + row * AST + cg * 4], &Kg[row * 64 + cg * 4]);
            cpa16(&Vs[s * 64 * VST + row * VST + cg * 4], &Vg[row * 64 + cg * 4]);
        }
        cp_commit();
    };

    load_kv(0, 0);

    float oacc[8][4];
#pragma unroll
    for (int j = 0; j < 8; j++)
#pragma unroll
        for (int q = 0; q < 4; q++) oacc[j][q] = 0.f;
    float mi0 = -1e30f, mi1 = -1e30f, li0 = 0.f, li1 = 0.f;

    for (int jt = 0; jt < SS / 64; jt++) {
        int buf = jt & 1;
        if (jt < SS / 64 - 1) {
            load_kv(buf ^ 1, jt + 1);
            cp_wait<1>();
        } else {
            cp_wait<0>();
        }
        __syncthreads();

        const float* Kb = &Ks[buf * 64 * AST];
        const float* Vb = &Vs[buf * 64 * VST];

        float s[8][4];
#pragma unroll
        for (int j = 0; j < 8; j++)
#pragma unroll
            for (int q = 0; q < 4; q++) s[j][q] = 0.f;

#pragma unroll
        for (int kk = 0; kk < 8; kk++) {
            unsigned b[8][2];
#pragma unroll
            for (int j = 0; j < 8; j++) {
                int n0 = j * 8 + r;
                b[j][0] = __float_as_uint(Kb[n0 * AST + kk * 8 + c]);
                b[j][1] = __float_as_uint(Kb[n0 * AST + kk * 8 + c + 4]);
            }
#pragma unroll
            for (int j = 0; j < 8; j++)
                mma8(s[j], qa[kk], b[j]);
        }

        float mx0 = -1e30f, mx1 = -1e30f;
#pragma unroll
        for (int j = 0; j < 8; j++) {
            mx0 = fmaxf(mx0, fmaxf(s[j][0], s[j][1]));
            mx1 = fmaxf(mx1, fmaxf(s[j][2], s[j][3]));
        }
        mx0 = fmaxf(mx0, __shfl_xor_sync(0xffffffffu, mx0, 1));
        mx0 = fmaxf(mx0, __shfl_xor_sync(0xffffffffu, mx0, 2));
        mx1 = fmaxf(mx1, __shfl_xor_sync(0xffffffffu, mx1, 1));
        mx1 = fmaxf(mx1, __shfl_xor_sync(0xffffffffu, mx1, 2));

        float mnew0 = fmaxf(mi0, mx0), mnew1 = fmaxf(mi1, mx1);
        float corr0 = __expf(mi0 - mnew0), corr1 = __expf(mi1 - mnew1);
        mi0 = mnew0; mi1 = mnew1;

        float sum0 = 0.f, sum1 = 0.f;
#pragma unroll
        for (int j = 0; j < 8; j++) {
            s[j][0] = __expf(s[j][0] - mnew0);
            s[j][1] = __expf(s[j][1] - mnew0);
            s[j][2] = __expf(s[j][2] - mnew1);
            s[j][3] = __expf(s[j][3] - mnew1);
            sum0 += s[j][0] + s[j][1];
            sum1 += s[j][2] + s[j][3];
        }
        sum0 += __shfl_xor_sync(0xffffffffu, sum0, 1);
        sum0 += __shfl_xor_sync(0xffffffffu, sum0, 2);
        sum1 += __shfl_xor_sync(0xffffffffu, sum1, 1);
        sum1 += __shfl_xor_sync(0xffffffffu, sum1, 2);
        li0 = li0 * corr0 + sum0;
        li1 = li1 * corr1 + sum1;

#pragma unroll
        for (int j = 0; j < 8; j++) {
            oacc[j][0] *= corr0; oacc[j][1] *= corr0;
            oacc[j][2] *= corr1; oacc[j][3] *= corr1;
        }

#pragma unroll
        for (int j = 0; j < 8; j++) {
            *(float2*)&Pw[r * AST + j * 8 + 2 * c] = make_float2(
                __uint_as_float(f2t(s[j][0])), __uint_as_float(f2t(s[j][1])));
            *(float2*)&Pw[(r + 8) * AST + j * 8 + 2 * c] = make_float2(
                __uint_as_float(f2t(s[j][2])), __uint_as_float(f2t(s[j][3])));
        }
        __syncwarp();

#pragma unroll
        for (int kk = 0; kk < 8; kk++) {
            unsigned a[4], b[8][2];
            a[0] = __float_as_uint(Pw[r * AST + kk * 8 + c]);
            a[1] = __float_as_uint(Pw[(r + 8) * AST + kk * 8 + c]);
            a[2] = __float_as_uint(Pw[r * AST + kk * 8 + c + 4]);
            a[3] = __float_as_uint(Pw[(r + 8) * AST + kk * 8 + c + 4]);
#pragma unroll
            for (int j = 0; j < 8; j++) {
                int n0 = j * 8 + r;
                b[j][0] = __float_as_uint(Vb[(kk * 8 + c) * VST + n0]);
                b[j][1] = __float_as_uint(Vb[(kk * 8 + c + 4) * VST + n0]);
            }
#pragma unroll
            for (int j = 0; j < 8; j++)
                mma8(oacc[j], a, b[j]);
        }
        __syncthreads();
    }

    const int b = bh >> 4, head = bh & 15;
    float inv0 = 1.f / li0, inv1 = 1.f / li1;
    size_t q0 = (size_t)b * SS + mblk * 64 + w * 16 + r;
#pragma unroll
    for (int j = 0; j < 8; j++) {
        int col = head * 64 + j * 8 + 2 * c;
        *(float2*)&g_Y[q0 * DD + col] = make_float2(
            __uint_as_float(f2t(oacc[j][0] * inv0)),
            __uint_as_float(f2t(oacc[j][1] * inv0)));
        *(float2*)&g_Y[(q0 + 8) * DD + col] = make_float2(
            __uint_as_float(f2t(oacc[j][2] * inv1)),
            __uint_as_float(f2t(oacc[j][3] * inv1)));
    }
}

// ---------------------------------------------------------------------------
extern "C" void kernel_launch(void* const* d_in, const int* in_sizes, int n_in,
                              void* d_out, int out_size)
{
    const float* x      = (const float*)d_in[0];
    const float* W_attn = (const float*)d_in[1];
    const float* b_attn = (const float*)d_in[2];
    const float* W_out  = (const float*)d_in[3];
    const float* b_out  = (const float*)d_in[4];
    float* out = (float*)d_out;

    (void)in_sizes; (void)n_in; (void)out_size;

    // 0) pre-round inputs to tf32 grid
    round_tf32_k<0><<<MROWS * DD / 4 / 256, 256>>>(x,      MROWS * DD / 4);
    round_tf32_k<1><<<3 * DD * DD / 4 / 256, 256>>>(W_attn, 3 * DD * DD / 4);
    round_tf32_k<2><<<DD * DD / 4 / 256, 256>>>(W_out,  DD * DD / 4);

    size_t gsm = (size_t)2 * NSTG * STGF * sizeof(float);   // 81920
    cudaFuncSetAttribute((const void*)gemm_tc<0>,
                         cudaFuncAttributeMaxDynamicSharedMemorySize, (int)gsm);
    cudaFuncSetAttribute((const void*)gemm_tc<1>,
                         cudaFuncAttributeMaxDynamicSharedMemorySize, (int)gsm);

    // 1) QKV projection -> rounded K/Q/V in [B,H,S,HD]
    gemm_tc<0><<<dim3(3072 / 128, MROWS / 128), 256, gsm>>>(b_attn, nullptr);

    // 2) flash attention v2 -> rounded Y in [B,S,D]
    size_t asm_ = (size_t)(2 * 64 * AST + 2 * 64 * VST + 4 * 16 * AST)
                  * sizeof(float);   // 89088
    cudaFuncSetAttribute((const void*)attn_tc,
                         cudaFuncAttributeMaxDynamicSharedMemorySize, (int)asm_);
    attn_tc<<<dim3(BB * HH, SS / 64), 128, asm_>>>();

    // 3) output projection (fp32 result)
    gemm_tc<1><<<dim3(1024 / 128, MROWS / 128), 256, gsm>>>(b_out, out);
}

// round 7
// speedup vs baseline: 1.0724x; 1.0724x over previous
#include <cuda_runtime.h>
#include <math.h>

#define BB 4
#define SS 2048
#define DD 1024
#define HH 16
#define HD 64
#define MROWS (BB * SS)   // 8192

// Scratch (allocation-free: __device__ globals)
__device__ float g_K[BB * HH * SS * HD];
__device__ float g_Q[BB * HH * SS * HD];
__device__ float g_V[BB * HH * SS * HD];
__device__ float g_Y[BB * SS * DD];
__device__ float g_xr[MROWS * DD];     // x rounded to tf32
__device__ float g_Wa[3 * DD * DD];    // W_attn rounded
__device__ float g_Wo[DD * DD];        // W_out rounded

// ---------------------------------------------------------------------------
// helpers
// ---------------------------------------------------------------------------
__device__ __forceinline__ unsigned f2t(float f) {
    unsigned u;
    asm("cvt.rna.tf32.f32 %0, %1;" : "=r"(u) : "f"(f));
    return u;
}

__device__ __forceinline__ void mma8(float* c, const unsigned* a, const unsigned* b) {
    asm volatile(
        "mma.sync.aligned.m16n8k8.row.col.f32.tf32.tf32.f32 "
        "{%0,%1,%2,%3}, {%4,%5,%6,%7}, {%8,%9}, {%0,%1,%2,%3};\n"
        : "+f"(c[0]), "+f"(c[1]), "+f"(c[2]), "+f"(c[3])
        : "r"(a[0]), "r"(a[1]), "r"(a[2]), "r"(a[3]), "r"(b[0]), "r"(b[1]));
}

__device__ __forceinline__ void cpa16(void* s, const void* g) {
    unsigned sa = (unsigned)__cvta_generic_to_shared(s);
    asm volatile("cp.async.cg.shared.global [%0], [%1], 16;\n"
                 :: "r"(sa), "l"(g) : "memory");
}
__device__ __forceinline__ void cp_commit() {
    asm volatile("cp.async.commit_group;\n" ::: "memory");
}
template <int N>
__device__ __forceinline__ void cp_wait() {
    asm volatile("cp.async.wait_group %0;\n" :: "n"(N) : "memory");
}

// ---------------------------------------------------------------------------
// Prep: round tensors to tf32-representable fp32 (TGT: 0=x, 1=W_attn, 2=W_out)
// ---------------------------------------------------------------------------
template <int TGT>
__global__ void round_tf32_k(const float* __restrict__ in, int n4) {
    float* outp = (TGT == 0) ? g_xr : (TGT == 1) ? g_Wa : g_Wo;
    int i = blockIdx.x * blockDim.x + threadIdx.x;
    if (i < n4) {
        float4 v = ((const float4*)in)[i];
        float4 o;
        o.x = __uint_as_float(f2t(v.x));
        o.y = __uint_as_float(f2t(v.y));
        o.z = __uint_as_float(f2t(v.z));
        o.w = __uint_as_float(f2t(v.w));
        ((float4*)outp)[i] = o;
    }
}

// ---------------------------------------------------------------------------
// TF32 GEMM, cp.async double-buffered (round-4 proven version).
// C[m,n]=sum_k A[m,k]*W[n,k]+bias[n]; BLK 128x128x32, 256 thr, warp 32x64.
// EPI==0: A=g_xr, W=g_Wa, scatter rounded into g_K/g_Q/g_V (split k,q,v)
// EPI==1: A=g_Y,  W=g_Wo, plain fp32 store + bias
// ---------------------------------------------------------------------------
#define GST 36

template <int EPI>
__global__ __launch_bounds__(256) void gemm_tc(
    const float* __restrict__ bias, float* __restrict__ out)
{
    const float* A = (EPI == 0) ? (const float*)g_xr : (const float*)g_Y;
    const float* W = (EPI == 0) ? (const float*)g_Wa : (const float*)g_Wo;
    extern __shared__ float dsm[];
    float* Asm = dsm;
    float* Bsm = dsm + 2 * 128 * GST;

    const int t = threadIdx.x, lane = t & 31, warp = t >> 5;
    const int wm = warp & 3, wn = warp >> 2;
    const int r = lane >> 2, c = lane & 3;
    const int mBase = blockIdx.y * 128, nBase = blockIdx.x * 128;

    float acc[2][8][4];
#pragma unroll
    for (int i = 0; i < 2; i++)
#pragma unroll
        for (int j = 0; j < 8; j++)
#pragma unroll
            for (int q = 0; q < 4; q++) acc[i][j][q] = 0.f;

    auto load_stage = [&](int s, int k0) {
#pragma unroll
        for (int u0 = 0; u0 < 4; u0++) {
            int u = t + u0 * 256;
            int row = u >> 3, cg = u & 7;
            cpa16(&Asm[s * 128 * GST + row * GST + cg * 4],
                  &A[(size_t)(mBase + row) * 1024 + k0 + cg * 4]);
            cpa16(&Bsm[s * 128 * GST + row * GST + cg * 4],
                  &W[(size_t)(nBase + row) * 1024 + k0 + cg * 4]);
        }
        cp_commit();
    };

    load_stage(0, 0);

    for (int kt = 0; kt < 32; kt++) {
        int buf = kt & 1;
        if (kt < 31) {
            load_stage(buf ^ 1, (kt + 1) * 32);
            cp_wait<1>();
        } else {
            cp_wait<0>();
        }
        __syncthreads();

        const float* Ab = &Asm[buf * 128 * GST];
        const float* Bb = &Bsm[buf * 128 * GST];
#pragma unroll
        for (int kk = 0; kk < 4; kk++) {
            unsigned a[2][4], b[8][2];
#pragma unroll
            for (int i = 0; i < 2; i++) {
                int m0 = wm * 32 + i * 16;
                a[i][0] = __float_as_uint(Ab[(m0 + r) * GST + kk * 8 + c]);
                a[i][1] = __float_as_uint(Ab[(m0 + r + 8) * GST + kk * 8 + c]);
                a[i][2] = __float_as_uint(Ab[(m0 + r) * GST + kk * 8 + c + 4]);
                a[i][3] = __float_as_uint(Ab[(m0 + r + 8) * GST + kk * 8 + c + 4]);
            }
#pragma unroll
            for (int j = 0; j < 8; j++) {
                int n0 = wn * 64 + j * 8 + r;
                b[j][0] = __float_as_uint(Bb[n0 * GST + kk * 8 + c]);
                b[j][1] = __float_as_uint(Bb[n0 * GST + kk * 8 + c + 4]);
            }
#pragma unroll
            for (int i = 0; i < 2; i++)
#pragma unroll
                for (int j = 0; j < 8; j++)
                    mma8(acc[i][j], a[i], b[j]);
        }
        __syncthreads();
    }

#pragma unroll
    for (int i = 0; i < 2; i++) {
#pragma unroll
        for (int j = 0; j < 8; j++) {
            int mg0 = mBase + wm * 32 + i * 16 + r;
            int ng = nBase + wn * 64 + j * 8 + 2 * c;
            if (EPI == 0) {
#pragma unroll
                for (int h = 0; h < 2; h++) {
                    int m = mg0 + h * 8;
                    int bb = m >> 11, s = m & 2047;
#pragma unroll
                    for (int e = 0; e < 2; e++) {
                        int n = ng + e;
                        float v = acc[i][j][h * 2 + e] + bias[n];
                        int chunk = n >> 10;   // 0=k,1=q,2=v
                        int d = n & 1023;
                        int hh = d >> 6, hd = d & 63;
                        size_t idx = ((size_t)(bb * HH + hh) * SS + s) * HD + hd;
                        float vr = __uint_as_float(f2t(v));
                        if (chunk == 0)      g_K[idx] = vr;
                        else if (chunk == 1) g_Q[idx] = vr;
                        else                 g_V[idx] = vr;
                    }
                }
            } else {
                float2 bv = *(const float2*)&bias[ng];
                *(float2*)&out[(size_t)mg0 * DD + ng] =
                    make_float2(acc[i][j][0] + bv.x, acc[i][j][1] + bv.y);
                *(float2*)&out[(size_t)(mg0 + 8) * DD + ng] =
                    make_float2(acc[i][j][2] + bv.x, acc[i][j][3] + bv.y);
            }
        }
    }
}

// ---------------------------------------------------------------------------
// Flash attention v3: 256 threads, 8 warps, CTA tile 128 q x 64 kv.
// Per-warp tile 16x64 (identical inner code to v2). Q in regs (pre-scaled),
// softmax in regs, P in per-warp smem. 2 CTAs/SM -> 16 warps/SM; each K/V
// tile load now serves 128 q-rows (traffic per unit work halved).
// ---------------------------------------------------------------------------
#define AST 68
#define VST 72

__global__ __launch_bounds__(256, 2) void attn_tc()
{
    extern __shared__ float dsa[];
    float* Ks = dsa;                      // [2][64][AST]
    float* Vs = Ks + 2 * 64 * AST;        // [2][64][VST]
    float* Ps = Vs + 2 * 64 * VST;        // [8][16][AST] per-warp

    const int t = threadIdx.x, lane = t & 31, w = t >> 5;   // w: 0..7
    const int r = lane >> 2, c = lane & 3;
    const int bh = blockIdx.x, mblk = blockIdx.y;

    const float* Qg  = g_Q + ((size_t)bh * SS + mblk * 128) * HD;
    const float* Kg0 = g_K + (size_t)bh * SS * HD;
    const float* Vg0 = g_V + (size_t)bh * SS * HD;

    float* Pw = Ps + w * 16 * AST;

    // Q fragments in registers, pre-scaled by 1/sqrt(64)=0.125 (exact on tf32)
    unsigned qa[8][4];
#pragma unroll
    for (int kk = 0; kk < 8; kk++) {
        qa[kk][0] = __float_as_uint(Qg[(w * 16 + r) * 64 + kk * 8 + c] * 0.125f);
        qa[kk][1] = __float_as_uint(Qg[(w * 16 + r + 8) * 64 + kk * 8 + c] * 0.125f);
        qa[kk][2] = __float_as_uint(Qg[(w * 16 + r) * 64 + kk * 8 + c + 4] * 0.125f);
        qa[kk][3] = __float_as_uint(Qg[(w * 16 + r + 8) * 64 + kk * 8 + c + 4] * 0.125f);
    }

    auto load_kv = [&](int s, int jt) {
        const float* Kg = Kg0 + (size_t)jt * 64 * HD;
        const float* Vg = Vg0 + (size_t)jt * 64 * HD;
#pragma unroll
        for (int u0 = 0; u0 < 4; u0++) {
            int u = t + u0 * 256;          // 0..1023
            int row = u >> 4, cg = u & 15;
            cpa16(&Ks[s * 64 * AST + row * AST + cg * 4], &Kg[row * 64 + cg * 4]);
            cpa16(&Vs[s * 64 * VST + row * VST + cg * 4], &Vg[row * 64 + cg * 4]);
        }
        cp_commit();
    };

    load_kv(0, 0);

    float oacc[8][4];
#pragma unroll
    for (int j = 0; j < 8; j++)
#pragma unroll
        for (int q = 0; q < 4; q++) oacc[j][q] = 0.f;
    float mi0 = -1e30f, mi1 = -1e30f, li0 = 0.f, li1 = 0.f;

    for (int jt = 0; jt < SS / 64; jt++) {
        int buf = jt & 1;
        if (jt < SS / 64 - 1) {
            load_kv(buf ^ 1, jt + 1);
            cp_wait<1>();
        } else {
            cp_wait<0>();
        }
        __syncthreads();   // K/V(buf) visible to all warps

        const float* Kb = &Ks[buf * 64 * AST];
        const float* Vb = &Vs[buf * 64 * VST];

        // --- scores S = (Q/8) @ K^T : warp tile 16 x 64 ---
        float s[8][4];
#pragma unroll
        for (int j = 0; j < 8; j++)
#pragma unroll
            for (int q = 0; q < 4; q++) s[j][q] = 0.f;

#pragma unroll
        for (int kk = 0; kk < 8; kk++) {
            unsigned b[8][2];
#pragma unroll
            for (int j = 0; j < 8; j++) {
                int n0 = j * 8 + r;
                b[j][0] = __float_as_uint(Kb[n0 * AST + kk * 8 + c]);
                b[j][1] = __float_as_uint(Kb[n0 * AST + kk * 8 + c + 4]);
            }
#pragma unroll
            for (int j = 0; j < 8; j++)
                mma8(s[j], qa[kk], b[j]);
        }

        // --- online softmax in registers ---
        float mx0 = -1e30f, mx1 = -1e30f;
#pragma unroll
        for (int j = 0; j < 8; j++) {
            mx0 = fmaxf(mx0, fmaxf(s[j][0], s[j][1]));
            mx1 = fmaxf(mx1, fmaxf(s[j][2], s[j][3]));
        }
        mx0 = fmaxf(mx0, __shfl_xor_sync(0xffffffffu, mx0, 1));
        mx0 = fmaxf(mx0, __shfl_xor_sync(0xffffffffu, mx0, 2));
        mx1 = fmaxf(mx1, __shfl_xor_sync(0xffffffffu, mx1, 1));
        mx1 = fmaxf(mx1, __shfl_xor_sync(0xffffffffu, mx1, 2));

        float mnew0 = fmaxf(mi0, mx0), mnew1 = fmaxf(mi1, mx1);
        float corr0 = __expf(mi0 - mnew0), corr1 = __expf(mi1 - mnew1);
        mi0 = mnew0; mi1 = mnew1;

        float sum0 = 0.f, sum1 = 0.f;
#pragma unroll
        for (int j = 0; j < 8; j++) {
            s[j][0] = __expf(s[j][0] - mnew0);
            s[j][1] = __expf(s[j][1] - mnew0);
            s[j][2] = __expf(s[j][2] - mnew1);
            s[j][3] = __expf(s[j][3] - mnew1);
            sum0 += s[j][0] + s[j][1];
            sum1 += s[j][2] + s[j][3];
        }
        sum0 += __shfl_xor_sync(0xffffffffu, sum0, 1);
        sum0 += __shfl_xor_sync(0xffffffffu, sum0, 2);
        sum1 += __shfl_xor_sync(0xffffffffu, sum1, 1);
        sum1 += __shfl_xor_sync(0xffffffffu, sum1, 2);
        li0 = li0 * corr0 + sum0;
        li1 = li1 * corr1 + sum1;

        // rescale O accumulators
#pragma unroll
        for (int j = 0; j < 8; j++) {
            oacc[j][0] *= corr0; oacc[j][1] *= corr0;
            oacc[j][2] *= corr1; oacc[j][3] *= corr1;
        }

        // --- P (tf32-rounded) to per-warp smem ---
#pragma unroll
        for (int j = 0; j < 8; j++) {
            *(float2*)&Pw[r * AST + j * 8 + 2 * c] = make_float2(
                __uint_as_float(f2t(s[j][0])), __uint_as_float(f2t(s[j][1])));
            *(float2*)&Pw[(r + 8) * AST + j * 8 + 2 * c] = make_float2(
                __uint_as_float(f2t(s[j][2])), __uint_as_float(f2t(s[j][3])));
        }
        __syncwarp();

        // --- O += P @ V ---
#pragma unroll
        for (int kk = 0; kk < 8; kk++) {
            unsigned a[4], b[8][2];
            a[0] = __float_as_uint(Pw[r * AST + kk * 8 + c]);
            a[1] = __float_as_uint(Pw[(r + 8) * AST + kk * 8 + c]);
            a[2] = __float_as_uint(Pw[r * AST + kk * 8 + c + 4]);
            a[3] = __float_as_uint(Pw[(r + 8) * AST + kk * 8 + c + 4]);
#pragma unroll
            for (int j = 0; j < 8; j++) {
                int n0 = j * 8 + r;
                b[j][0] = __float_as_uint(Vb[(kk * 8 + c) * VST + n0]);
                b[j][1] = __float_as_uint(Vb[(kk * 8 + c + 4) * VST + n0]);
            }
#pragma unroll
            for (int j = 0; j < 8; j++)
                mma8(oacc[j], a, b[j]);
        }
        __syncthreads();   // all warps done with buf before it is refilled
    }

    // --- normalize + write rounded to g_Y [B,S,D] ---
    const int b = bh >> 4, head = bh & 15;
    float inv0 = 1.f / li0, inv1 = 1.f / li1;
    size_t q0 = (size_t)b * SS + mblk * 128 + w * 16 + r;
#pragma unroll
    for (int j = 0; j < 8; j++) {
        int col = head * 64 + j * 8 + 2 * c;
        *(float2*)&g_Y[q0 * DD + col] = make_float2(
            __uint_as_float(f2t(oacc[j][0] * inv0)),
            __uint_as_float(f2t(oacc[j][1] * inv0)));
        *(float2*)&g_Y[(q0 + 8) * DD + col] = make_float2(
            __uint_as_float(f2t(oacc[j][2] * inv1)),
            __uint_as_float(f2t(oacc[j][3] * inv1)));
    }
}

// ---------------------------------------------------------------------------
extern "C" void kernel_launch(void* const* d_in, const int* in_sizes, int n_in,
                              void* d_out, int out_size)
{
    const float* x      = (const float*)d_in[0];
    const float* W_attn = (const float*)d_in[1];
    const float* b_attn = (const float*)d_in[2];
    const float* W_out  = (const float*)d_in[3];
    const float* b_out  = (const float*)d_in[4];
    float* out = (float*)d_out;

    (void)in_sizes; (void)n_in; (void)out_size;

    // 0) pre-round inputs to tf32 grid
    round_tf32_k<0><<<MROWS * DD / 4 / 256, 256>>>(x,      MROWS * DD / 4);
    round_tf32_k<1><<<3 * DD * DD / 4 / 256, 256>>>(W_attn, 3 * DD * DD / 4);
    round_tf32_k<2><<<DD * DD / 4 / 256, 256>>>(W_out,  DD * DD / 4);

    size_t gsm = (size_t)2 * 2 * 128 * GST * sizeof(float);   // 73728
    cudaFuncSetAttribute((const void*)gemm_tc<0>,
                         cudaFuncAttributeMaxDynamicSharedMemorySize, (int)gsm);
    cudaFuncSetAttribute((const void*)gemm_tc<1>,
                         cudaFuncAttributeMaxDynamicSharedMemorySize, (int)gsm);

    // 1) QKV projection -> rounded K/Q/V in [B,H,S,HD]
    gemm_tc<0><<<dim3(3072 / 128, MROWS / 128), 256, gsm>>>(b_attn, nullptr);

    // 2) flash attention v3 (128q x 64kv, 8 warps) -> rounded Y in [B,S,D]
    size_t asm_ = (size_t)(2 * 64 * AST + 2 * 64 * VST + 8 * 16 * AST)
                  * sizeof(float);   // 106496
    cudaFuncSetAttribute((const void*)attn_tc,
                         cudaFuncAttributeMaxDynamicSharedMemorySize, (int)asm_);
    attn_tc<<<dim3(BB * HH, SS / 128), 256, asm_>>>();

    // 3) output projection (fp32 result)
    gemm_tc<1><<<dim3(1024 / 128, MROWS / 128), 256, gsm>>>(b_out, out);
}

// round 9
// speedup vs baseline: 1.8979x; 1.7697x over previous
#include <cuda_runtime.h>
#include <cuda_fp16.h>
#include <math.h>

#define BB 4
#define SS 2048
#define DD 1024
#define HH 16
#define HD 64
#define MROWS (BB * SS)   // 8192

// Scratch (allocation-free: __device__ globals) — fp16 intermediates
__device__ __half g_Kh[BB * HH * SS * HD];
__device__ __half g_Qh[BB * HH * SS * HD];
__device__ __half g_Vt[BB * HH * HD * SS];   // V transposed per head: [hd][seq]
__device__ __half g_Yh[MROWS * DD];
__device__ __half g_xh[MROWS * DD];
__device__ __half g_Wah[3 * DD * DD];
__device__ __half g_Woh[DD * DD];

// ---------------------------------------------------------------------------
// helpers
// ---------------------------------------------------------------------------
__device__ __forceinline__ void mma16(float* c, const unsigned* a, const unsigned* b) {
    asm volatile(
        "mma.sync.aligned.m16n8k16.row.col.f32.f16.f16.f32 "
        "{%0,%1,%2,%3}, {%4,%5,%6,%7}, {%8,%9}, {%0,%1,%2,%3};\n"
        : "+f"(c[0]), "+f"(c[1]), "+f"(c[2]), "+f"(c[3])
        : "r"(a[0]), "r"(a[1]), "r"(a[2]), "r"(a[3]), "r"(b[0]), "r"(b[1]));
}

__device__ __forceinline__ void cpa16(void* s, const void* g) {
    unsigned sa = (unsigned)__cvta_generic_to_shared(s);
    asm volatile("cp.async.cg.shared.global [%0], [%1], 16;\n"
                 :: "r"(sa), "l"(g) : "memory");
}
__device__ __forceinline__ void cp_commit() {
    asm volatile("cp.async.commit_group;\n" ::: "memory");
}
template <int N>
__device__ __forceinline__ void cp_wait() {
    asm volatile("cp.async.wait_group %0;\n" :: "n"(N) : "memory");
}

__device__ __forceinline__ unsigned pack_h2(float a, float b) {
    __half2 h = __floats2half2_rn(a, b);
    return *reinterpret_cast<unsigned*>(&h);
}

// ---------------------------------------------------------------------------
// Prep: fp32 -> fp16 (TGT: 0=x, 1=W_attn, 2=W_out)
// ---------------------------------------------------------------------------
template <int TGT>
__global__ void to_half_k(const float* __restrict__ in, int n4) {
    __half* outp = (TGT == 0) ? g_xh : (TGT == 1) ? g_Wah : g_Woh;
    int i = blockIdx.x * blockDim.x + threadIdx.x;
    if (i < n4) {
        float4 v = ((const float4*)in)[i];
        unsigned lo = pack_h2(v.x, v.y);
        unsigned hi = pack_h2(v.z, v.w);
        ((uint2*)outp)[i] = make_uint2(lo, hi);
    }
}

// ---------------------------------------------------------------------------
// FP16 GEMM, cp.async double-buffered. C[m,n]=sum_k A[m,k]*W[n,k]+bias[n]
// BLK 128x128, stage k=64 halfs, 256 thr (8 warps 4m x 2n), warp 32x64,
// mma m16n8k16. Smem rows: 64 halfs data, stride 72 halfs (36 words).
// EPI==0: A=g_xh, W=g_Wah, scatter half into g_Kh/g_Qh/g_Vt (split k,q,v;
//         V transposed to [hd][seq])
// EPI==1: A=g_Yh, W=g_Woh, fp32 store + bias
// Dynamic smem: 2 ops x 2 stages x 128 rows x 144 B = 73728 B.
// ---------------------------------------------------------------------------
#define GSW 36                 // row stride in 32-bit words
#define GSTGW (128 * GSW)      // words per operand stage

template <int EPI>
__global__ __launch_bounds__(256) void gemm_fp16(
    const float* __restrict__ bias, float* __restrict__ out)
{
    const __half* A = (EPI == 0) ? (const __half*)g_xh : (const __half*)g_Yh;
    const __half* W = (EPI == 0) ? (const __half*)g_Wah : (const __half*)g_Woh;
    extern __shared__ unsigned smw[];
    unsigned* Asm = smw;                   // [2][GSTGW]
    unsigned* Bsm = smw + 2 * GSTGW;       // [2][GSTGW]

    const int t = threadIdx.x, lane = t & 31, warp = t >> 5;
    const int wm = warp & 3, wn = warp >> 2;
    const int r = lane >> 2, c = lane & 3;
    const int mBase = blockIdx.y * 128, nBase = blockIdx.x * 128;

    float acc[2][8][4];
#pragma unroll
    for (int i = 0; i < 2; i++)
#pragma unroll
        for (int j = 0; j < 8; j++)
#pragma unroll
            for (int q = 0; q < 4; q++) acc[i][j][q] = 0.f;

    // stage loader: 128 rows x 8 chunks(16B) per operand
    auto load_stage = [&](int s, int k0) {
#pragma unroll
        for (int u0 = 0; u0 < 4; u0++) {
            int u = t + u0 * 256;            // 0..1023
            int row = u >> 3, cg = u & 7;
            cpa16(&Asm[s * GSTGW + row * GSW + cg * 4],
                  A + (size_t)(mBase + row) * 1024 + k0 + cg * 8);
            cpa16(&Bsm[s * GSTGW + row * GSW + cg * 4],
                  W + (size_t)(nBase + row) * 1024 + k0 + cg * 8);
        }
        cp_commit();
    };

    load_stage(0, 0);

    for (int kt = 0; kt < 16; kt++) {        // 16 stages x k=64
        int buf = kt & 1;
        if (kt < 15) {
            load_stage(buf ^ 1, (kt + 1) * 64);
            cp_wait<1>();
        } else {
            cp_wait<0>();
        }
        __syncthreads();

        const unsigned* Ab = &Asm[buf * GSTGW];
        const unsigned* Bb = &Bsm[buf * GSTGW];
#pragma unroll
        for (int kk = 0; kk < 4; kk++) {     // k16 per step
            unsigned a[2][4], b[8][2];
#pragma unroll
            for (int i = 0; i < 2; i++) {
                int m0 = wm * 32 + i * 16;
                a[i][0] = Ab[(m0 + r) * GSW + kk * 8 + c];
                a[i][1] = Ab[(m0 + r + 8) * GSW + kk * 8 + c];
                a[i][2] = Ab[(m0 + r) * GSW + kk * 8 + c + 4];
                a[i][3] = Ab[(m0 + r + 8) * GSW + kk * 8 + c + 4];
            }
#pragma unroll
            for (int j = 0; j < 8; j++) {
                int n0 = wn * 64 + j * 8 + r;
                b[j][0] = Bb[n0 * GSW + kk * 8 + c];
                b[j][1] = Bb[n0 * GSW + kk * 8 + c + 4];
            }
#pragma unroll
            for (int i = 0; i < 2; i++)
#pragma unroll
                for (int j = 0; j < 8; j++)
                    mma16(acc[i][j], a[i], b[j]);
        }
        __syncthreads();
    }

#pragma unroll
    for (int i = 0; i < 2; i++) {
#pragma unroll
        for (int j = 0; j < 8; j++) {
            int mg0 = mBase + wm * 32 + i * 16 + r;
            int ng = nBase + wn * 64 + j * 8 + 2 * c;
            if (EPI == 0) {
#pragma unroll
                for (int h = 0; h < 2; h++) {
                    int m = mg0 + h * 8;
                    int bb = m >> 11, s = m & 2047;
#pragma unroll
                    for (int e = 0; e < 2; e++) {
                        int n = ng + e;
                        float v = acc[i][j][h * 2 + e] + bias[n];
                        __half vh = __float2half_rn(v);
                        int chunk = n >> 10;   // 0=k,1=q,2=v
                        int d = n & 1023;
                        int hh = d >> 6, hd = d & 63;
                        int head = bb * HH + hh;
                        if (chunk == 0)
                            g_Kh[((size_t)head * SS + s) * HD + hd] = vh;
                        else if (chunk == 1)
                            g_Qh[((size_t)head * SS + s) * HD + hd] = vh;
                        else
                            g_Vt[((size_t)head * HD + hd) * SS + s] = vh;
                    }
                }
            } else {
                float2 bv = *(const float2*)&bias[ng];
                *(float2*)&out[(size_t)mg0 * DD + ng] =
                    make_float2(acc[i][j][0] + bv.x, acc[i][j][1] + bv.y);
                *(float2*)&out[(size_t)(mg0 + 8) * DD + ng] =
                    make_float2(acc[i][j][2] + bv.x, acc[i][j][3] + bv.y);
            }
        }
    }
}

// ---------------------------------------------------------------------------
// Flash attention fp16: 256 threads, 8 warps, CTA tile 128 q x 64 kv.
// Warp tile 16x64. Q frags in regs (pre-scaled 1/8), softmax in fp32 regs,
// P half2 in per-warp smem (stride 36 words — FIXED from 20), V from g_Vt.
// smem: Ks[2][64][36w] + Vs[2][64][36w] + Ps[8][16][36w] = 55296 B.
// ---------------------------------------------------------------------------
#define KSW 36   // K/V row stride (words)
#define PSW 36   // P row stride (words) — row data = 32 words, padded

__global__ __launch_bounds__(256, 2) void attn_fp16()
{
    extern __shared__ unsigned smw[];
    unsigned* Ksw = smw;                         // [2][64*KSW]
    unsigned* Vsw = Ksw + 2 * 64 * KSW;          // [2][64*KSW]
    unsigned* Psw = Vsw + 2 * 64 * KSW;          // [8][16*PSW]

    const int t = threadIdx.x, lane = t & 31, w = t >> 5;   // w 0..7
    const int r = lane >> 2, c = lane & 3;
    const int bh = blockIdx.x, mblk = blockIdx.y;

    const __half* Qg  = g_Qh + ((size_t)bh * SS + mblk * 128) * HD;
    const __half* Kg0 = g_Kh + (size_t)bh * SS * HD;
    const __half* Vt0 = g_Vt + (size_t)bh * HD * SS;

    unsigned* Pw = Psw + w * 16 * PSW;

    // Q fragments (m16n8k16 A layout), pre-scaled by 0.125 (exact)
    unsigned qa[4][4];
#pragma unroll
    for (int kk = 0; kk < 4; kk++) {
#pragma unroll
        for (int z = 0; z < 4; z++) {
            int row = w * 16 + r + ((z & 1) ? 8 : 0);
            int col = kk * 16 + 2 * c + ((z & 2) ? 8 : 0);
            __half2 h = *reinterpret_cast<const __half2*>(&Qg[(size_t)row * HD + col]);
            float2 f = __half22float2(h);
            qa[kk][z] = pack_h2(f.x * 0.125f, f.y * 0.125f);
        }
    }

    auto load_kv = [&](int s, int jt) {
#pragma unroll
        for (int u0 = 0; u0 < 2; u0++) {
            int u = t + u0 * 256;                // 0..511
            int row = u >> 3, cg = u & 7;
            cpa16(&Ksw[s * 64 * KSW + row * KSW + cg * 4],
                  Kg0 + (size_t)(jt * 64 + row) * HD + cg * 8);
            cpa16(&Vsw[s * 64 * KSW + row * KSW + cg * 4],
                  Vt0 + (size_t)row * SS + jt * 64 + cg * 8);
        }
        cp_commit();
    };

    load_kv(0, 0);

    float oacc[8][4];
#pragma unroll
    for (int j = 0; j < 8; j++)
#pragma unroll
        for (int q = 0; q < 4; q++) oacc[j][q] = 0.f;
    float mi0 = -1e30f, mi1 = -1e30f, li0 = 0.f, li1 = 0.f;

    for (int jt = 0; jt < SS / 64; jt++) {
        int buf = jt & 1;
        if (jt < SS / 64 - 1) {
            load_kv(buf ^ 1, jt + 1);
            cp_wait<1>();
        } else {
            cp_wait<0>();
        }
        __syncthreads();

        const unsigned* Kb = &Ksw[buf * 64 * KSW];
        const unsigned* Vb = &Vsw[buf * 64 * KSW];

        // --- scores S = (Q/8) @ K^T ---
        float s[8][4];
#pragma unroll
        for (int j = 0; j < 8; j++)
#pragma unroll
            for (int q = 0; q < 4; q++) s[j][q] = 0.f;

#pragma unroll
        for (int kk = 0; kk < 4; kk++) {
            unsigned b[8][2];
#pragma unroll
            for (int j = 0; j < 8; j++) {
                int n0 = j * 8 + r;
                b[j][0] = Kb[n0 * KSW + kk * 8 + c];
                b[j][1] = Kb[n0 * KSW + kk * 8 + c + 4];
            }
#pragma unroll
            for (int j = 0; j < 8; j++)
                mma16(s[j], qa[kk], b[j]);
        }

        // --- online softmax in registers ---
        float mx0 = -1e30f, mx1 = -1e30f;
#pragma unroll
        for (int j = 0; j < 8; j++) {
            mx0 = fmaxf(mx0, fmaxf(s[j][0], s[j][1]));
            mx1 = fmaxf(mx1, fmaxf(s[j][2], s[j][3]));
        }
        mx0 = fmaxf(mx0, __shfl_xor_sync(0xffffffffu, mx0, 1));
        mx0 = fmaxf(mx0, __shfl_xor_sync(0xffffffffu, mx0, 2));
        mx1 = fmaxf(mx1, __shfl_xor_sync(0xffffffffu, mx1, 1));
        mx1 = fmaxf(mx1, __shfl_xor_sync(0xffffffffu, mx1, 2));

        float mnew0 = fmaxf(mi0, mx0), mnew1 = fmaxf(mi1, mx1);
        float corr0 = __expf(mi0 - mnew0), corr1 = __expf(mi1 - mnew1);
        mi0 = mnew0; mi1 = mnew1;

        float sum0 = 0.f, sum1 = 0.f;
#pragma unroll
        for (int j = 0; j < 8; j++) {
            s[j][0] = __expf(s[j][0] - mnew0);
            s[j][1] = __expf(s[j][1] - mnew0);
            s[j][2] = __expf(s[j][2] - mnew1);
            s[j][3] = __expf(s[j][3] - mnew1);
            sum0 += s[j][0] + s[j][1];
            sum1 += s[j][2] + s[j][3];
        }
        sum0 += __shfl_xor_sync(0xffffffffu, sum0, 1);
        sum0 += __shfl_xor_sync(0xffffffffu, sum0, 2);
        sum1 += __shfl_xor_sync(0xffffffffu, sum1, 1);
        sum1 += __shfl_xor_sync(0xffffffffu, sum1, 2);
        li0 = li0 * corr0 + sum0;
        li1 = li1 * corr1 + sum1;

#pragma unroll
        for (int j = 0; j < 8; j++) {
            oacc[j][0] *= corr0; oacc[j][1] *= corr0;
            oacc[j][2] *= corr1; oacc[j][3] *= corr1;
        }

        // --- P (half2) to per-warp smem ---
#pragma unroll
        for (int j = 0; j < 8; j++) {
            Pw[r * PSW + j * 4 + c]       = pack_h2(s[j][0], s[j][1]);
            Pw[(r + 8) * PSW + j * 4 + c] = pack_h2(s[j][2], s[j][3]);
        }
        __syncwarp();

        // --- O += P @ V  (V from transposed layout: k-contiguous pairs) ---
#pragma unroll
        for (int kk = 0; kk < 4; kk++) {
            unsigned a[4], b[8][2];
            a[0] = Pw[r * PSW + kk * 8 + c];
            a[1] = Pw[(r + 8) * PSW + kk * 8 + c];
            a[2] = Pw[r * PSW + kk * 8 + c + 4];
            a[3] = Pw[(r + 8) * PSW + kk * 8 + c + 4];
#pragma unroll
            for (int j = 0; j < 8; j++) {
                int n0 = j * 8 + r;
                b[j][0] = Vb[n0 * KSW + kk * 8 + c];
                b[j][1] = Vb[n0 * KSW + kk * 8 + c + 4];
            }
#pragma unroll
            for (int j = 0; j < 8; j++)
                mma16(oacc[j], a, b[j]);
        }
        __syncthreads();
    }

    // --- normalize + write half to g_Yh [B,S,D] ---
    const int b = bh >> 4, head = bh & 15;
    float inv0 = 1.f / li0, inv1 = 1.f / li1;
    size_t q0 = (size_t)b * SS + mblk * 128 + w * 16 + r;
#pragma unroll
    for (int j = 0; j < 8; j++) {
        int col = head * 64 + j * 8 + 2 * c;
        *reinterpret_cast<__half2*>(&g_Yh[q0 * DD + col]) =
            __floats2half2_rn(oacc[j][0] * inv0, oacc[j][1] * inv0);
        *reinterpret_cast<__half2*>(&g_Yh[(q0 + 8) * DD + col]) =
            __floats2half2_rn(oacc[j][2] * inv1, oacc[j][3] * inv1);
    }
}

// ---------------------------------------------------------------------------
extern "C" void kernel_launch(void* const* d_in, const int* in_sizes, int n_in,
                              void* d_out, int out_size)
{
    const float* x      = (const float*)d_in[0];
    const float* W_attn = (const float*)d_in[1];
    const float* b_attn = (const float*)d_in[2];
    const float* W_out  = (const float*)d_in[3];
    const float* b_out  = (const float*)d_in[4];
    float* out = (float*)d_out;

    (void)in_sizes; (void)n_in; (void)out_size;

    // 0) fp32 -> fp16 prep
    to_half_k<0><<<MROWS * DD / 4 / 256, 256>>>(x,      MROWS * DD / 4);
    to_half_k<1><<<3 * DD * DD / 4 / 256, 256>>>(W_attn, 3 * DD * DD / 4);
    to_half_k<2><<<DD * DD / 4 / 256, 256>>>(W_out,  DD * DD / 4);

    size_t gsm = (size_t)4 * GSTGW * sizeof(unsigned);   // 73728
    cudaFuncSetAttribute((const void*)gemm_fp16<0>,
                         cudaFuncAttributeMaxDynamicSharedMemorySize, (int)gsm);
    cudaFuncSetAttribute((const void*)gemm_fp16<1>,
                         cudaFuncAttributeMaxDynamicSharedMemorySize, (int)gsm);

    // 1) QKV projection -> g_Kh/g_Qh (seq-major) + g_Vt (hd-major)
    gemm_fp16<0><<<dim3(3072 / 128, MROWS / 128), 256, gsm>>>(b_attn, nullptr);

    // 2) flash attention fp16 -> g_Yh
    size_t asm_ = (size_t)(2 * 64 * KSW + 2 * 64 * KSW + 8 * 16 * PSW)
                  * sizeof(unsigned);   // 55296
    cudaFuncSetAttribute((const void*)attn_fp16,
                         cudaFuncAttributeMaxDynamicSharedMemorySize, (int)asm_);
    attn_fp16<<<dim3(BB * HH, SS / 128), 256, asm_>>>();

    // 3) output projection (fp32 result)
    gemm_fp16<1><<<dim3(1024 / 128, MROWS / 128), 256, gsm>>>(b_out, out);
}

// round 10
// speedup vs baseline: 2.0544x; 1.0825x over previous
#include <cuda_runtime.h>
#include <cuda_fp16.h>
#include <math.h>

#define BB 4
#define SS 2048
#define DD 1024
#define HH 16
#define HD 64
#define MROWS (BB * SS)   // 8192

// Scratch (allocation-free: __device__ globals) — fp16 intermediates
__device__ __half g_Kh[BB * HH * SS * HD];
__device__ __half g_Qh[BB * HH * SS * HD];
__device__ __half g_Vt[BB * HH * HD * SS];   // V transposed per head: [hd][seq]
__device__ __half g_Yh[MROWS * DD];
__device__ __half g_xh[MROWS * DD];
__device__ __half g_Wah[3 * DD * DD];
__device__ __half g_Woh[DD * DD];

// ---------------------------------------------------------------------------
// helpers
// ---------------------------------------------------------------------------
__device__ __forceinline__ void mma16(float* c, const unsigned* a, const unsigned* b) {
    asm volatile(
        "mma.sync.aligned.m16n8k16.row.col.f32.f16.f16.f32 "
        "{%0,%1,%2,%3}, {%4,%5,%6,%7}, {%8,%9}, {%0,%1,%2,%3};\n"
        : "+f"(c[0]), "+f"(c[1]), "+f"(c[2]), "+f"(c[3])
        : "r"(a[0]), "r"(a[1]), "r"(a[2]), "r"(a[3]), "r"(b[0]), "r"(b[1]));
}

__device__ __forceinline__ void ldsm4(unsigned& r0, unsigned& r1,
                                      unsigned& r2, unsigned& r3, unsigned a) {
    asm volatile("ldmatrix.sync.aligned.m8n8.x4.shared.b16 {%0,%1,%2,%3}, [%4];"
                 : "=r"(r0), "=r"(r1), "=r"(r2), "=r"(r3) : "r"(a));
}

__device__ __forceinline__ unsigned sm32(const void* p) {
    return (unsigned)__cvta_generic_to_shared(p);
}

__device__ __forceinline__ void cpa16(void* s, const void* g) {
    unsigned sa = (unsigned)__cvta_generic_to_shared(s);
    asm volatile("cp.async.cg.shared.global [%0], [%1], 16;\n"
                 :: "r"(sa), "l"(g) : "memory");
}
__device__ __forceinline__ void cp_commit() {
    asm volatile("cp.async.commit_group;\n" ::: "memory");
}
template <int N>
__device__ __forceinline__ void cp_wait() {
    asm volatile("cp.async.wait_group %0;\n" :: "n"(N) : "memory");
}

__device__ __forceinline__ unsigned pack_h2(float a, float b) {
    __half2 h = __floats2half2_rn(a, b);
    return *reinterpret_cast<unsigned*>(&h);
}

// ---------------------------------------------------------------------------
// Prep: fp32 -> fp16 (TGT: 0=x, 1=W_attn, 2=W_out)
// ---------------------------------------------------------------------------
template <int TGT>
__global__ void to_half_k(const float* __restrict__ in, int n4) {
    __half* outp = (TGT == 0) ? g_xh : (TGT == 1) ? g_Wah : g_Woh;
    int i = blockIdx.x * blockDim.x + threadIdx.x;
    if (i < n4) {
        float4 v = ((const float4*)in)[i];
        unsigned lo = pack_h2(v.x, v.y);
        unsigned hi = pack_h2(v.z, v.w);
        ((uint2*)outp)[i] = make_uint2(lo, hi);
    }
}

// ---------------------------------------------------------------------------
// FP16 GEMM, cp.async double-buffered, ldmatrix fragment loads.
// C[m,n]=sum_k A[m,k]*W[n,k]+bias[n]; BLK 128x128, stage k=64 halfs,
// 256 thr (8 warps 4m x 2n), warp 32x64, mma m16n8k16.
// EPI==0: A=g_xh, W=g_Wah, scatter half into g_Kh/g_Qh/g_Vt
// EPI==1: A=g_Yh, W=g_Woh, fp32 store + bias
// ---------------------------------------------------------------------------
#define GSW 36                 // row stride in 32-bit words
#define GSTGW (128 * GSW)      // words per operand stage

template <int EPI>
__global__ __launch_bounds__(256, 2) void gemm_fp16(
    const float* __restrict__ bias, float* __restrict__ out)
{
    const __half* A = (EPI == 0) ? (const __half*)g_xh : (const __half*)g_Yh;
    const __half* W = (EPI == 0) ? (const __half*)g_Wah : (const __half*)g_Woh;
    extern __shared__ unsigned smw[];
    unsigned* Asm = smw;                   // [2][GSTGW]
    unsigned* Bsm = smw + 2 * GSTGW;       // [2][GSTGW]

    const int t = threadIdx.x, lane = t & 31, warp = t >> 5;
    const int wm = warp & 3, wn = warp >> 2;
    const int r = lane >> 2, c = lane & 3;
    const int mBase = blockIdx.y * 128, nBase = blockIdx.x * 128;

    // ldmatrix lane address offsets (bytes within a stage)
    const int quad = lane >> 3, l8 = lane & 7;
    unsigned aoff[2], boff[4];
#pragma unroll
    for (int i = 0; i < 2; i++)
        aoff[i] = ((wm * 32 + i * 16 + l8 + (quad & 1) * 8) * GSW +
                   (quad >> 1) * 4) * 4;
#pragma unroll
    for (int jj = 0; jj < 4; jj++)
        boff[jj] = ((wn * 64 + jj * 16 + (quad >> 1) * 8 + l8) * GSW +
                    (quad & 1) * 4) * 4;

    const unsigned asm_base = sm32(Asm), bsm_base = sm32(Bsm);

    float acc[2][8][4];
#pragma unroll
    for (int i = 0; i < 2; i++)
#pragma unroll
        for (int j = 0; j < 8; j++)
#pragma unroll
            for (int q = 0; q < 4; q++) acc[i][j][q] = 0.f;

    auto load_stage = [&](int s, int k0) {
#pragma unroll
        for (int u0 = 0; u0 < 4; u0++) {
            int u = t + u0 * 256;            // 0..1023
            int row = u >> 3, cg = u & 7;
            cpa16(&Asm[s * GSTGW + row * GSW + cg * 4],
                  A + (size_t)(mBase + row) * 1024 + k0 + cg * 8);
            cpa16(&Bsm[s * GSTGW + row * GSW + cg * 4],
                  W + (size_t)(nBase + row) * 1024 + k0 + cg * 8);
        }
        cp_commit();
    };

    load_stage(0, 0);

    for (int kt = 0; kt < 16; kt++) {        // 16 stages x k=64
        int buf = kt & 1;
        if (kt < 15) {
            load_stage(buf ^ 1, (kt + 1) * 64);
            cp_wait<1>();
        } else {
            cp_wait<0>();
        }
        __syncthreads();

        const unsigned ab = asm_base + buf * GSTGW * 4;
        const unsigned bb = bsm_base + buf * GSTGW * 4;
#pragma unroll
        for (int kk = 0; kk < 4; kk++) {     // k16 per step
            unsigned a[2][4], bf[4][4];
#pragma unroll
            for (int i = 0; i < 2; i++)
                ldsm4(a[i][0], a[i][1], a[i][2], a[i][3], ab + aoff[i] + kk * 32);
#pragma unroll
            for (int jj = 0; jj < 4; jj++)
                ldsm4(bf[jj][0], bf[jj][1], bf[jj][2], bf[jj][3],
                      bb + boff[jj] + kk * 32);
#pragma unroll
            for (int i = 0; i < 2; i++)
#pragma unroll
                for (int j = 0; j < 8; j++)
                    mma16(acc[i][j], a[i], &bf[j >> 1][(j & 1) * 2]);
        }
        __syncthreads();
    }

#pragma unroll
    for (int i = 0; i < 2; i++) {
#pragma unroll
        for (int j = 0; j < 8; j++) {
            int mg0 = mBase + wm * 32 + i * 16 + r;
            int ng = nBase + wn * 64 + j * 8 + 2 * c;
            if (EPI == 0) {
#pragma unroll
                for (int h = 0; h < 2; h++) {
                    int m = mg0 + h * 8;
                    int bb2 = m >> 11, s = m & 2047;
#pragma unroll
                    for (int e = 0; e < 2; e++) {
                        int n = ng + e;
                        float v = acc[i][j][h * 2 + e] + bias[n];
                        __half vh = __float2half_rn(v);
                        int chunk = n >> 10;   // 0=k,1=q,2=v
                        int d = n & 1023;
                        int hh = d >> 6, hd = d & 63;
                        int head = bb2 * HH + hh;
                        if (chunk == 0)
                            g_Kh[((size_t)head * SS + s) * HD + hd] = vh;
                        else if (chunk == 1)
                            g_Qh[((size_t)head * SS + s) * HD + hd] = vh;
                        else
                            g_Vt[((size_t)head * HD + hd) * SS + s] = vh;
                    }
                }
            } else {
                float2 bv = *(const float2*)&bias[ng];
                *(float2*)&out[(size_t)mg0 * DD + ng] =
                    make_float2(acc[i][j][0] + bv.x, acc[i][j][1] + bv.y);
                *(float2*)&out[(size_t)(mg0 + 8) * DD + ng] =
                    make_float2(acc[i][j][2] + bv.x, acc[i][j][3] + bv.y);
            }
        }
    }
}

// ---------------------------------------------------------------------------
// Flash attention fp16 + ldmatrix: 256 threads, 8 warps, CTA 128q x 64kv.
// Warp tile 16x64. Q frags in regs (pre-scaled 1/8), softmax in fp32 regs,
// P half2 in per-warp smem, V from g_Vt. K/V/P frags via ldmatrix.x4.
// smem: Ks[2][64][36w] + Vs[2][64][36w] + Ps[8][16][36w] = 55296 B.
// ---------------------------------------------------------------------------
#define KSW 36   // K/V row stride (words)
#define PSW 36   // P row stride (words)

__global__ __launch_bounds__(256, 2) void attn_fp16()
{
    extern __shared__ unsigned smw[];
    unsigned* Ksw = smw;                         // [2][64*KSW]
    unsigned* Vsw = Ksw + 2 * 64 * KSW;          // [2][64*KSW]
    unsigned* Psw = Vsw + 2 * 64 * KSW;          // [8][16*PSW]

    const int t = threadIdx.x, lane = t & 31, w = t >> 5;   // w 0..7
    const int r = lane >> 2, c = lane & 3;
    const int bh = blockIdx.x, mblk = blockIdx.y;

    const __half* Qg  = g_Qh + ((size_t)bh * SS + mblk * 128) * HD;
    const __half* Kg0 = g_Kh + (size_t)bh * SS * HD;
    const __half* Vt0 = g_Vt + (size_t)bh * HD * SS;

    unsigned* Pw = Psw + w * 16 * PSW;

    // ldmatrix lane offsets
    const int quad = lane >> 3, l8 = lane & 7;
    unsigned nboff[4];                    // K/V B-frag offsets (bytes in tile)
#pragma unroll
    for (int jj = 0; jj < 4; jj++)
        nboff[jj] = ((jj * 16 + (quad >> 1) * 8 + l8) * KSW + (quad & 1) * 4) * 4;
    const unsigned paoff =                 // P A-frag offset (bytes in warp P)
        ((l8 + (quad & 1) * 8) * PSW + (quad >> 1) * 4) * 4;

    const unsigned ksm = sm32(Ksw), vsm = sm32(Vsw), psm = sm32(Pw);

    // Q fragments (m16n8k16 A layout), pre-scaled by 0.125 (exact)
    unsigned qa[4][4];
#pragma unroll
    for (int kk = 0; kk < 4; kk++) {
#pragma unroll
        for (int z = 0; z < 4; z++) {
            int row = w * 16 + r + ((z & 1) ? 8 : 0);
            int col = kk * 16 + 2 * c + ((z & 2) ? 8 : 0);
            __half2 h = *reinterpret_cast<const __half2*>(&Qg[(size_t)row * HD + col]);
            float2 f = __half22float2(h);
            qa[kk][z] = pack_h2(f.x * 0.125f, f.y * 0.125f);
        }
    }

    auto load_kv = [&](int s, int jt) {
#pragma unroll
        for (int u0 = 0; u0 < 2; u0++) {
            int u = t + u0 * 256;                // 0..511
            int row = u >> 3, cg = u & 7;
            cpa16(&Ksw[s * 64 * KSW + row * KSW + cg * 4],
                  Kg0 + (size_t)(jt * 64 + row) * HD + cg * 8);
            cpa16(&Vsw[s * 64 * KSW + row * KSW + cg * 4],
                  Vt0 + (size_t)row * SS + jt * 64 + cg * 8);
        }
        cp_commit();
    };

    load_kv(0, 0);

    float oacc[8][4];
#pragma unroll
    for (int j = 0; j < 8; j++)
#pragma unroll
        for (int q = 0; q < 4; q++) oacc[j][q] = 0.f;
    float mi0 = -1e30f, mi1 = -1e30f, li0 = 0.f, li1 = 0.f;

    for (int jt = 0; jt < SS / 64; jt++) {
        int buf = jt & 1;
        if (jt < SS / 64 - 1) {
            load_kv(buf ^ 1, jt + 1);
            cp_wait<1>();
        } else {
            cp_wait<0>();
        }
        __syncthreads();

        const unsigned kb = ksm + buf * 64 * KSW * 4;
        const unsigned vb = vsm + buf * 64 * KSW * 4;

        // --- scores S = (Q/8) @ K^T ---
        float s[8][4];
#pragma unroll
        for (int j = 0; j < 8; j++)
#pragma unroll
            for (int q = 0; q < 4; q++) s[j][q] = 0.f;

#pragma unroll
        for (int kk = 0; kk < 4; kk++) {
            unsigned bf[4][4];
#pragma unroll
            for (int jj = 0; jj < 4; jj++)
                ldsm4(bf[jj][0], bf[jj][1], bf[jj][2], bf[jj][3],
                      kb + nboff[jj] + kk * 32);
#pragma unroll
            for (int j = 0; j < 8; j++)
                mma16(s[j], qa[kk], &bf[j >> 1][(j & 1) * 2]);
        }

        // --- online softmax in registers ---
        float mx0 = -1e30f, mx1 = -1e30f;
#pragma unroll
        for (int j = 0; j < 8; j++) {
            mx0 = fmaxf(mx0, fmaxf(s[j][0], s[j][1]));
            mx1 = fmaxf(mx1, fmaxf(s[j][2], s[j][3]));
        }
        mx0 = fmaxf(mx0, __shfl_xor_sync(0xffffffffu, mx0, 1));
        mx0 = fmaxf(mx0, __shfl_xor_sync(0xffffffffu, mx0, 2));
        mx1 = fmaxf(mx1, __shfl_xor_sync(0xffffffffu, mx1, 1));
        mx1 = fmaxf(mx1, __shfl_xor_sync(0xffffffffu, mx1, 2));

        float mnew0 = fmaxf(mi0, mx0), mnew1 = fmaxf(mi1, mx1);
        float corr0 = __expf(mi0 - mnew0), corr1 = __expf(mi1 - mnew1);
        mi0 = mnew0; mi1 = mnew1;

        float sum0 = 0.f, sum1 = 0.f;
#pragma unroll
        for (int j = 0; j < 8; j++) {
            s[j][0] = __expf(s[j][0] - mnew0);
            s[j][1] = __expf(s[j][1] - mnew0);
            s[j][2] = __expf(s[j][2] - mnew1);
            s[j][3] = __expf(s[j][3] - mnew1);
            sum0 += s[j][0] + s[j][1];
            sum1 += s[j][2] + s[j][3];
        }
        sum0 += __shfl_xor_sync(0xffffffffu, sum0, 1);
        sum0 += __shfl_xor_sync(0xffffffffu, sum0, 2);
        sum1 += __shfl_xor_sync(0xffffffffu, sum1, 1);
        sum1 += __shfl_xor_sync(0xffffffffu, sum1, 2);
        li0 = li0 * corr0 + sum0;
        li1 = li1 * corr1 + sum1;

#pragma unroll
        for (int j = 0; j < 8; j++) {
            oacc[j][0] *= corr0; oacc[j][1] *= corr0;
            oacc[j][2] *= corr1; oacc[j][3] *= corr1;
        }

        // --- P (half2) to per-warp smem ---
#pragma unroll
        for (int j = 0; j < 8; j++) {
            Pw[r * PSW + j * 4 + c]       = pack_h2(s[j][0], s[j][1]);
            Pw[(r + 8) * PSW + j * 4 + c] = pack_h2(s[j][2], s[j][3]);
        }
        __syncwarp();

        // --- O += P @ V ---
#pragma unroll
        for (int kk = 0; kk < 4; kk++) {
            unsigned a[4], bf[4][4];
            ldsm4(a[0], a[1], a[2], a[3], psm + paoff + kk * 32);
#pragma unroll
            for (int jj = 0; jj < 4; jj++)
                ldsm4(bf[jj][0], bf[jj][1], bf[jj][2], bf[jj][3],
                      vb + nboff[jj] + kk * 32);
#pragma unroll
            for (int j = 0; j < 8; j++)
                mma16(oacc[j], a, &bf[j >> 1][(j & 1) * 2]);
        }
        __syncthreads();
    }

    // --- normalize + write half to g_Yh [B,S,D] ---
    const int b = bh >> 4, head = bh & 15;
    float inv0 = 1.f / li0, inv1 = 1.f / li1;
    size_t q0 = (size_t)b * SS + mblk * 128 + w * 16 + r;
#pragma unroll
    for (int j = 0; j < 8; j++) {
        int col = head * 64 + j * 8 + 2 * c;
        *reinterpret_cast<__half2*>(&g_Yh[q0 * DD + col]) =
            __floats2half2_rn(oacc[j][0] * inv0, oacc[j][1] * inv0);
        *reinterpret_cast<__half2*>(&g_Yh[(q0 + 8) * DD + col]) =
            __floats2half2_rn(oacc[j][2] * inv1, oacc[j][3] * inv1);
    }
}

// ---------------------------------------------------------------------------
extern "C" void kernel_launch(void* const* d_in, const int* in_sizes, int n_in,
                              void* d_out, int out_size)
{
    const float* x      = (const float*)d_in[0];
    const float* W_attn = (const float*)d_in[1];
    const float* b_attn = (const float*)d_in[2];
    const float* W_out  = (const float*)d_in[3];
    const float* b_out  = (const float*)d_in[4];
    float* out = (float*)d_out;

    (void)in_sizes; (void)n_in; (void)out_size;

    // 0) fp32 -> fp16 prep
    to_half_k<0><<<MROWS * DD / 4 / 256, 256>>>(x,      MROWS * DD / 4);
    to_half_k<1><<<3 * DD * DD / 4 / 256, 256>>>(W_attn, 3 * DD * DD / 4);
    to_half_k<2><<<DD * DD / 4 / 256, 256>>>(W_out,  DD * DD / 4);

    size_t gsm = (size_t)4 * GSTGW * sizeof(unsigned);   // 73728
    cudaFuncSetAttribute((const void*)gemm_fp16<0>,
                         cudaFuncAttributeMaxDynamicSharedMemorySize, (int)gsm);
    cudaFuncSetAttribute((const void*)gemm_fp16<1>,
                         cudaFuncAttributeMaxDynamicSharedMemorySize, (int)gsm);

    // 1) QKV projection -> g_Kh/g_Qh (seq-major) + g_Vt (hd-major)
    gemm_fp16<0><<<dim3(3072 / 128, MROWS / 128), 256, gsm>>>(b_attn, nullptr);

    // 2) flash attention fp16 -> g_Yh
    size_t asm_ = (size_t)(2 * 64 * KSW + 2 * 64 * KSW + 8 * 16 * PSW)
                  * sizeof(unsigned);   // 55296
    cudaFuncSetAttribute((const void*)attn_fp16,
                         cudaFuncAttributeMaxDynamicSharedMemorySize, (int)asm_);
    attn_fp16<<<dim3(BB * HH, SS / 128), 256, asm_>>>();

    // 3) output projection (fp32 result)
    gemm_fp16<1><<<dim3(1024 / 128, MROWS / 128), 256, gsm>>>(b_out, out);
}